// round 3
// baseline (speedup 1.0000x reference)
#include <cuda_runtime.h>

// ---------------------------------------------------------------------------
// Problem constants
// ---------------------------------------------------------------------------
#define BATCH   32
#define TT      512
#define EE      128
#define NHH     16
#define HDD     8
#define G3      384          // 3*E gates
#define BBS     96           // 3 branches * 32

typedef unsigned long long ull;

// ---------------------------------------------------------------------------
// Scratch (device globals: allocation-free per harness rules)
// q/k/v layout: t-major  [bh][t][d]  (bh = s*16+h):  idx = bh*4096 + t*8 + d
// ---------------------------------------------------------------------------
__device__ float g_q[BBS * NHH * TT * HDD];
__device__ float g_k[BBS * NHH * TT * HDD];
__device__ float g_v[BBS * NHH * TT * HDD];
__device__ float g_coor[BBS * EE];
__device__ float g_omean[BBS * EE];

// ---------------------------------------------------------------------------
// f32x2 packed helpers (sm_100+)
// ---------------------------------------------------------------------------
__device__ __forceinline__ ull f2fma(ull a, ull b, ull c) {
    ull d;
    asm("fma.rn.f32x2 %0, %1, %2, %3;" : "=l"(d) : "l"(a), "l"(b), "l"(c));
    return d;
}
__device__ __forceinline__ float hsum2(ull a) {
    float x, y;
    asm("mov.b64 {%0, %1}, %2;" : "=f"(x), "=f"(y) : "l"(a));
    return x + y;
}
__device__ __forceinline__ ull f2pack(float x, float y) {
    ull r;
    asm("mov.b64 %0, {%1, %2};" : "=l"(r) : "f"(x), "f"(y));
    return r;
}
__device__ __forceinline__ void f2unpack(ull a, float& x, float& y) {
    asm("mov.b64 {%0, %1}, %2;" : "=f"(x), "=f"(y) : "l"(a));
}

// sigmoid(x) = rcp(1 + exp2(-x*log2e));  rel err ~1e-6
__device__ __forceinline__ float fsigmoid(float x) {
    float e;
    asm("ex2.approx.f32 %0, %1;" : "=f"(e) : "f"(x * -1.4426950408889634f));
    float r;
    asm("rcp.approx.f32 %0, %1;" : "=f"(r) : "f"(1.0f + e));
    return r;
}
// tanh(x) = 1 - 2*rcp(1 + exp2(2x*log2e));  rel err ~1e-6 (NOT tanh.approx)
__device__ __forceinline__ float ftanh(float x) {
    float e;
    asm("ex2.approx.f32 %0, %1;" : "=f"(e) : "f"(x * 2.8853900817779268f));
    float r;
    asm("rcp.approx.f32 %0, %1;" : "=f"(r) : "f"(1.0f + e));
    return 1.0f - 2.0f * r;
}
__device__ __forceinline__ float fex2(float x) {
    float p;
    asm("ex2.approx.f32 %0, %1;" : "=f"(p) : "f"(x));
    return p;
}

// ---------------------------------------------------------------------------
// Kernel 1: GRU over 512 steps. One block per sequence (96 blocks, 384 thr).
// Thread g owns gate-row g: w_hh[g][:] in 64 packed f32x2 registers.
// h loads from smem via LDS.128 (ulonglong2) to stay off the LDS wavefront
// ceiling (matvec floor = 384 cyc/step on the FMA pipe).
// ---------------------------------------------------------------------------
__global__ void __launch_bounds__(384, 1)
gru_kernel(const float* __restrict__ a_in, const float* __restrict__ p_in,
           const float* __restrict__ n_in,
           const int* __restrict__ a_len, const int* __restrict__ p_len,
           const int* __restrict__ n_len,
           const float* __restrict__ w_ih, const float* __restrict__ w_hh,
           const float* __restrict__ b_ih, const float* __restrict__ b_hh)
{
    const int s  = blockIdx.x;          // 0..95
    const int br = s >> 5;
    const int b  = s & 31;
    const float* inp = (br == 0 ? a_in : (br == 1 ? p_in : n_in)) + b * TT * 4;
    const int* lens  = (br == 0 ? a_len : (br == 1 ? p_len : n_len));
    const int len    = lens[b];

    const int g = threadIdx.x;          // 0..383

    const float wih0 = w_ih[g * 2 + 0];
    const float wih1 = w_ih[g * 2 + 1];
    const float bih  = b_ih[g];
    const float bhh  = b_hh[g];

    ull w2[64];
    {
        const ulonglong2* wr = (const ulonglong2*)(w_hh + g * EE);
#pragma unroll
        for (int i = 0; i < 32; ++i) {
            const ulonglong2 t = wr[i];
            w2[2 * i + 0] = t.x;
            w2[2 * i + 1] = t.y;
        }
    }

    __shared__ __align__(16) float hsf[EE];
    __shared__ float hg[G3];
    __shared__ float xgs[G3];

    if (g < EE) hsf[g] = 0.0f;
    __syncthreads();

    const ulonglong2* hs4 = (const ulonglong2*)hsf;

    for (int t = 0; t < TT; ++t) {
        const float2 x01 = *(const float2*)(inp + t * 4);
        xgs[g] = fmaf(wih0, x01.x, fmaf(wih1, x01.y, bih));

        ull acc0 = 0ull, acc1 = 0ull, acc2 = 0ull, acc3 = 0ull;
#pragma unroll
        for (int i = 0; i < 16; ++i) {
            const ulonglong2 h01 = hs4[2 * i + 0];
            const ulonglong2 h23 = hs4[2 * i + 1];
            acc0 = f2fma(w2[4 * i + 0], h01.x, acc0);
            acc1 = f2fma(w2[4 * i + 1], h01.y, acc1);
            acc2 = f2fma(w2[4 * i + 2], h23.x, acc2);
            acc3 = f2fma(w2[4 * i + 3], h23.y, acc3);
        }
        hg[g] = (hsum2(acc0) + hsum2(acc1)) + (hsum2(acc2) + hsum2(acc3)) + bhh;
        __syncthreads();

        if (g < EE) {
            const float r  = fsigmoid(xgs[g] + hg[g]);
            const float z  = fsigmoid(xgs[g + 128] + hg[g + 128]);
            const float nn = ftanh(fmaf(r, hg[g + 256], xgs[g + 256]));
            const float h2 = fmaf(z, hsf[g] - nn, nn);   // (1-z)*n + z*h
            hsf[g] = h2;
            if (t == len - 1) g_coor[s * EE + g] = h2;
        }
        __syncthreads();
    }
}

// ---------------------------------------------------------------------------
// Kernel 2: fused m + QKV GEMM.
// m[s,t,k] = lookup(grid) + posres(grid + pe(t)) computed on the fly.
// C[49152 x 384] = m @ attn_in_w^T + b.  Tiles: 128 rows x 128 cols (one col
// tile per q/k/v part), K staged in two 64-chunks.  8x8 micro-tiles with
// f32x2 accumulators (FMA-pipe bound).  Epilogue stages C through smem and
// emits coalesced float4 stores into t-major q/k/v.
// Tile stride 136 floats: 16B-aligned rows, B-store conflicts 8-way -> 4-way.
// ---------------------------------------------------------------------------
#define TSTR 136

__global__ void __launch_bounds__(256)
qkv_gemm_kernel(const float* __restrict__ a_in, const float* __restrict__ p_in,
                const float* __restrict__ n_in,
                const float* __restrict__ lw, const float* __restrict__ lb,
                const float* __restrict__ pw, const float* __restrict__ pb,
                const float* __restrict__ in_w, const float* __restrict__ in_b)
{
    const int bx   = blockIdx.x;     // 0..383 : s = bx>>2, t0 = (bx&3)*128
    const int part = blockIdx.y;     // 0..2   : q / k / v
    const int s  = bx >> 2;
    const int t0 = (bx & 3) * 128;
    const int tid = threadIdx.x;
    const int tx = tid & 15;
    const int ty = tid >> 4;

    extern __shared__ __align__(16) float dynsm[];
    float* As = dynsm;                 // [64][TSTR]
    float* Bs = dynsm + 64 * TSTR;     // [64][TSTR]
    float* Cs = dynsm;                 // [128][TSTR] (aliases As+Bs exactly)

    __shared__ float rg0[128], rg1[128], rsn[128], rcs[128];
    __shared__ float lw0s[128], lw1s[128], lbs[128];
    __shared__ float pw0s[128], pw1s[128], pbs[128];
    __shared__ float bias_s[128];

    if (tid < 128) {
        const int t = t0 + tid;
        const int br = s >> 5;
        const int b = s & 31;
        const float* inp = (br == 0 ? a_in : (br == 1 ? p_in : n_in));
        const float2 gg = *(const float2*)(inp + ((b << 9) + t) * 4 + 2);
        rg0[tid] = gg.x;
        rg1[tid] = gg.y;
        rsn[tid] = sinf((float)t);
        rcs[tid] = cosf((float)t);
        lw0s[tid] = lw[2 * tid];
        lw1s[tid] = lw[2 * tid + 1];
        lbs[tid]  = lb[tid];
        pw0s[tid] = pw[2 * tid];
        pw1s[tid] = pw[2 * tid + 1];
        pbs[tid]  = pb[tid];
        bias_s[tid] = in_b[part * 128 + tid];
    }
    __syncthreads();

    ull acc2[8][4];
#pragma unroll
    for (int i = 0; i < 8; ++i)
#pragma unroll
        for (int j = 0; j < 4; ++j) acc2[i][j] = 0ull;

    for (int kc = 0; kc < 2; ++kc) {
        // A tile: compute m for 64 k-rows x 128 t-cols (conflict-free stores)
        for (int idx = tid; idx < 64 * 128; idx += 256) {
            const int kk = idx >> 7;
            const int tl = idx & 127;
            const int k = kc * 64 + kk;
            const float g0 = rg0[tl], g1 = rg1[tl];
            float m = fmaf(lw0s[k], g0, fmaf(lw1s[k], g1, lbs[k]));
            m += fmaf(pw0s[k], g0 + rsn[tl],
                      fmaf(pw1s[k], g1 + rcs[tl], pbs[k]));
            As[kk * TSTR + tl] = m;
        }
        // B tile: in_w rows (coalesced 64-float global runs)
        for (int idx = tid; idx < 64 * 128; idx += 256) {
            const int kkl = idx & 63;
            const int cl  = idx >> 6;
            Bs[kkl * TSTR + cl] = in_w[(part * 128 + cl) * EE + kc * 64 + kkl];
        }
        __syncthreads();

#pragma unroll 4
        for (int kk = 0; kk < 64; ++kk) {
            const float4 a0 = *(const float4*)(As + kk * TSTR + ty * 8);
            const float4 a1 = *(const float4*)(As + kk * TSTR + ty * 8 + 4);
            const ulonglong2 b01 = *(const ulonglong2*)(Bs + kk * TSTR + tx * 8);
            const ulonglong2 b23 = *(const ulonglong2*)(Bs + kk * TSTR + tx * 8 + 4);
            const float av[8] = {a0.x, a0.y, a0.z, a0.w, a1.x, a1.y, a1.z, a1.w};
#pragma unroll
            for (int i = 0; i < 8; ++i) {
                const ull ap = f2pack(av[i], av[i]);
                acc2[i][0] = f2fma(ap, b01.x, acc2[i][0]);
                acc2[i][1] = f2fma(ap, b01.y, acc2[i][1]);
                acc2[i][2] = f2fma(ap, b23.x, acc2[i][2]);
                acc2[i][3] = f2fma(ap, b23.y, acc2[i][3]);
            }
        }
        __syncthreads();
    }

    // epilogue: stage C in smem (aliases As/Bs; safe after the trailing sync)
#pragma unroll
    for (int i = 0; i < 8; ++i) {
        const int r = ty * 8 + i;
#pragma unroll
        for (int j = 0; j < 4; ++j)
            *(ull*)(Cs + r * TSTR + tx * 8 + 2 * j) = acc2[i][j];
    }
    __syncthreads();

    float* G = (part == 0 ? g_q : (part == 1 ? g_k : g_v));
    for (int it = 0; it < 8; ++it) {
        const int idx = it * 256 + tid;
        const int tl = idx & 127;
        const int hq = idx >> 7;       // head 0..15
        float4 c0 = *(const float4*)(Cs + tl * TSTR + hq * 8);
        float4 c1 = *(const float4*)(Cs + tl * TSTR + hq * 8 + 4);
        c0.x += bias_s[hq * 8 + 0]; c0.y += bias_s[hq * 8 + 1];
        c0.z += bias_s[hq * 8 + 2]; c0.w += bias_s[hq * 8 + 3];
        c1.x += bias_s[hq * 8 + 4]; c1.y += bias_s[hq * 8 + 5];
        c1.z += bias_s[hq * 8 + 6]; c1.w += bias_s[hq * 8 + 7];
        const int addr = (s * NHH + hq) * 4096 + (t0 + tl) * 8;
        *(float4*)(G + addr)     = c0;
        *(float4*)(G + addr + 4) = c1;
    }
}

// ---------------------------------------------------------------------------
// Kernel 3: attention per (s, h) block (1536 blocks, 256 threads).
// t-major k/v staged in smem; each LANE owns 2 whole queries -> no per-query
// cross-lane reduction; k/v come as broadcast LDS.128.  Softmax without
// max-subtraction (scores are O(3e-3)); scale and log2e folded into q.
// o is mean-pooled over queries in-kernel (mean o linear == linear o mean,
// so the out-projection GEMM collapses to a 96x128x128 matvec in kernel 4).
// ---------------------------------------------------------------------------
__global__ void __launch_bounds__(256)
attn_kernel()
{
    const int bh = blockIdx.x;          // 0..1535
    const int s = bh >> 4;
    const int tid = threadIdx.x;
    const int w = tid >> 5;
    const int lane = tid & 31;

    __shared__ __align__(16) float ks[TT * HDD];
    __shared__ __align__(16) float vs[TT * HDD];
    __shared__ float osum_s[8][8];

    {
        const float4* kg = (const float4*)(g_k + bh * 4096);
        const float4* vg = (const float4*)(g_v + bh * 4096);
        float4* k4 = (float4*)ks;
        float4* v4 = (float4*)vs;
        for (int i = tid; i < 1024; i += 256) {
            k4[i] = kg[i];
            v4[i] = vg[i];
        }
    }
    __syncthreads();

    // scale * log2e folded into q
    const float cst = 0.35355339059327373f * 1.4426950408889634f;

    ull qa[2][4];
    {
        const float* qp = g_q + bh * 4096;
        const int qi[2] = { w * 64 + lane, w * 64 + lane + 32 };
#pragma unroll
        for (int qq = 0; qq < 2; ++qq) {
            const float4 x0 = *(const float4*)(qp + qi[qq] * 8);
            const float4 x1 = *(const float4*)(qp + qi[qq] * 8 + 4);
            qa[qq][0] = f2pack(x0.x * cst, x0.y * cst);
            qa[qq][1] = f2pack(x0.z * cst, x0.w * cst);
            qa[qq][2] = f2pack(x1.x * cst, x1.y * cst);
            qa[qq][3] = f2pack(x1.z * cst, x1.w * cst);
        }
    }

    ull pv[2][4];
    float sume[2] = {0.0f, 0.0f};
#pragma unroll
    for (int qq = 0; qq < 2; ++qq)
#pragma unroll
        for (int j = 0; j < 4; ++j) pv[qq][j] = 0ull;

#pragma unroll 4
    for (int t = 0; t < TT; ++t) {
        const ulonglong2 k01 = *(const ulonglong2*)(ks + t * 8);
        const ulonglong2 k23 = *(const ulonglong2*)(ks + t * 8 + 4);
        const ulonglong2 v01 = *(const ulonglong2*)(vs + t * 8);
        const ulonglong2 v23 = *(const ulonglong2*)(vs + t * 8 + 4);
#pragma unroll
        for (int qq = 0; qq < 2; ++qq) {
            ull sa = f2fma(qa[qq][0], k01.x, 0ull);
            sa = f2fma(qa[qq][1], k01.y, sa);
            sa = f2fma(qa[qq][2], k23.x, sa);
            sa = f2fma(qa[qq][3], k23.y, sa);
            const float p = fex2(hsum2(sa));   // exp(score)
            sume[qq] += p;
            const ull pp = f2pack(p, p);
            pv[qq][0] = f2fma(pp, v01.x, pv[qq][0]);
            pv[qq][1] = f2fma(pp, v01.y, pv[qq][1]);
            pv[qq][2] = f2fma(pp, v23.x, pv[qq][2]);
            pv[qq][3] = f2fma(pp, v23.y, pv[qq][3]);
        }
    }

    float oacc[8];
#pragma unroll
    for (int d = 0; d < 8; ++d) oacc[d] = 0.0f;
#pragma unroll
    for (int qq = 0; qq < 2; ++qq) {
        const float inv = 1.0f / sume[qq];
#pragma unroll
        for (int j = 0; j < 4; ++j) {
            float x, y;
            f2unpack(pv[qq][j], x, y);
            oacc[2 * j]     = fmaf(x, inv, oacc[2 * j]);
            oacc[2 * j + 1] = fmaf(y, inv, oacc[2 * j + 1]);
        }
    }
    // one cross-lane reduction per warp (not per query)
#pragma unroll
    for (int d = 0; d < 8; ++d) {
#pragma unroll
        for (int off = 16; off > 0; off >>= 1)
            oacc[d] += __shfl_xor_sync(0xffffffffu, oacc[d], off);
    }
    if (lane == 0) {
#pragma unroll
        for (int d = 0; d < 8; ++d) osum_s[w][d] = oacc[d];
    }
    __syncthreads();
    if (tid < 8) {
        float t = 0.0f;
#pragma unroll
        for (int ww = 0; ww < 8; ++ww) t += osum_s[ww][tid];
        g_omean[s * EE + (bh & 15) * 8 + tid] = t * (1.0f / 512.0f);
    }
}

// ---------------------------------------------------------------------------
// Kernel 4: output projection of mean (mean o linear == linear o mean) + mix.
// ---------------------------------------------------------------------------
__global__ void __launch_bounds__(128)
proj_kernel(const float* __restrict__ out_w, const float* __restrict__ out_b,
            const float* __restrict__ gamma_p, float* __restrict__ out)
{
    const int s = blockIdx.x;   // 0..95
    const int e = threadIdx.x;  // 0..127

    __shared__ __align__(16) float om[EE];
    om[e] = g_omean[s * EE + e];
    __syncthreads();

    float acc = out_b[e];
    const float* wr = out_w + e * EE;
#pragma unroll 8
    for (int k = 0; k < EE; ++k) acc = fmaf(wr[k], om[k], acc);

    const float g = *gamma_p;
    out[s * EE + e] = g * g_coor[s * EE + e] + (1.0f - g) * acc;
}

// ---------------------------------------------------------------------------
// Kernel 5: triplet distances.
// ---------------------------------------------------------------------------
__global__ void __launch_bounds__(128)
dist_kernel(float* __restrict__ out)
{
    const int b = blockIdx.x;   // 0..31
    const int e = threadIdx.x;  // 0..127

    const float av = out[b * EE + e];
    const float pe = out[4096 + b * EE + e];
    const float ne = out[8192 + b * EE + e];
    const float dp = av - pe + 1e-6f;
    const float dn = av - ne + 1e-6f;
    float sp = dp * dp;
    float sn = dn * dn;
#pragma unroll
    for (int off = 16; off > 0; off >>= 1) {
        sp += __shfl_xor_sync(0xffffffffu, sp, off);
        sn += __shfl_xor_sync(0xffffffffu, sn, off);
    }
    __shared__ float rp[4], rn[4];
    if ((e & 31) == 0) { rp[e >> 5] = sp; rn[e >> 5] = sn; }
    __syncthreads();
    if (e == 0) {
        const float tp = rp[0] + rp[1] + rp[2] + rp[3];
        const float tn = rn[0] + rn[1] + rn[2] + rn[3];
        out[12288 + b] = expf(-sqrtf(tp));
        out[12320 + b] = expf(-sqrtf(tn));
    }
}

// ---------------------------------------------------------------------------
// Launch
// ---------------------------------------------------------------------------
extern "C" void kernel_launch(void* const* d_in, const int* in_sizes, int n_in,
                              void* d_out, int out_size)
{
    const float* anchor = (const float*)d_in[0];
    const float* pos    = (const float*)d_in[1];
    const float* neg    = (const float*)d_in[2];
    const int*   alen   = (const int*)d_in[3];
    const int*   plen   = (const int*)d_in[4];
    const int*   nlen   = (const int*)d_in[5];
    const float* w_ih   = (const float*)d_in[6];
    const float* w_hh   = (const float*)d_in[7];
    const float* b_ih   = (const float*)d_in[8];
    const float* b_hh   = (const float*)d_in[9];
    const float* lw     = (const float*)d_in[10];
    const float* lb     = (const float*)d_in[11];
    const float* pw     = (const float*)d_in[12];
    const float* pb     = (const float*)d_in[13];
    const float* in_w   = (const float*)d_in[14];
    const float* in_b   = (const float*)d_in[15];
    const float* out_w  = (const float*)d_in[16];
    const float* out_b  = (const float*)d_in[17];
    const float* gamma  = (const float*)d_in[18];
    float* out = (float*)d_out;

    const int qkv_smem = 2 * 64 * TSTR * (int)sizeof(float);   // 69632 B
    cudaFuncSetAttribute(qkv_gemm_kernel,
                         cudaFuncAttributeMaxDynamicSharedMemorySize, qkv_smem);

    gru_kernel<<<BBS, 384>>>(anchor, pos, neg, alen, plen, nlen,
                             w_ih, w_hh, b_ih, b_hh);
    qkv_gemm_kernel<<<dim3(384, 3), 256, qkv_smem>>>(anchor, pos, neg,
                                                     lw, lb, pw, pb, in_w, in_b);
    attn_kernel<<<BBS * NHH, 256>>>();
    proj_kernel<<<BBS, 128>>>(out_w, out_b, gamma, out);
    dist_kernel<<<BATCH, 128>>>(out);
}

// round 6
// speedup vs baseline: 1.1903x; 1.1903x over previous
#include <cuda_runtime.h>

// ---------------------------------------------------------------------------
// Problem constants
// ---------------------------------------------------------------------------
#define BATCH   32
#define TT      512
#define EE      128
#define NHH     16
#define HDD     8
#define G3      384          // 3*E gates
#define BBS     96           // 3 branches * 32

typedef unsigned long long ull;

// ---------------------------------------------------------------------------
// Scratch (device globals: allocation-free per harness rules)
// q/k/v layout: t-major  [bh][t][d]  (bh = s*16+h):  idx = bh*4096 + t*8 + d
// ---------------------------------------------------------------------------
__device__ float g_q[BBS * NHH * TT * HDD];
__device__ float g_k[BBS * NHH * TT * HDD];
__device__ float g_v[BBS * NHH * TT * HDD];
__device__ float g_coor[BBS * EE];
__device__ float g_omean[BBS * EE];

// ---------------------------------------------------------------------------
// f32x2 packed helpers (sm_100+)
// ---------------------------------------------------------------------------
__device__ __forceinline__ ull f2fma(ull a, ull b, ull c) {
    ull d;
    asm("fma.rn.f32x2 %0, %1, %2, %3;" : "=l"(d) : "l"(a), "l"(b), "l"(c));
    return d;
}
__device__ __forceinline__ float hsum2(ull a) {
    float x, y;
    asm("mov.b64 {%0, %1}, %2;" : "=f"(x), "=f"(y) : "l"(a));
    return x + y;
}
__device__ __forceinline__ ull f2pack(float x, float y) {
    ull r;
    asm("mov.b64 %0, {%1, %2};" : "=l"(r) : "f"(x), "f"(y));
    return r;
}
__device__ __forceinline__ void f2unpack(ull a, float& x, float& y) {
    asm("mov.b64 {%0, %1}, %2;" : "=f"(x), "=f"(y) : "l"(a));
}

// sigmoid(x) = rcp(1 + exp2(-x*log2e));  rel err ~1e-6
__device__ __forceinline__ float fsigmoid(float x) {
    float e;
    asm("ex2.approx.f32 %0, %1;" : "=f"(e) : "f"(x * -1.4426950408889634f));
    float r;
    asm("rcp.approx.f32 %0, %1;" : "=f"(r) : "f"(1.0f + e));
    return r;
}
// tanh(x) = 1 - 2*rcp(1 + exp2(2x*log2e));  rel err ~1e-6 (NOT tanh.approx)
__device__ __forceinline__ float ftanh(float x) {
    float e;
    asm("ex2.approx.f32 %0, %1;" : "=f"(e) : "f"(x * 2.8853900817779268f));
    float r;
    asm("rcp.approx.f32 %0, %1;" : "=f"(r) : "f"(1.0f + e));
    return 1.0f - 2.0f * r;
}
__device__ __forceinline__ float fex2(float x) {
    float p;
    asm("ex2.approx.f32 %0, %1;" : "=f"(p) : "f"(x));
    return p;
}

// ---------------------------------------------------------------------------
// Kernel 1: GRU over 512 steps. One block per sequence (96 blocks, 384 thr).
// Thread g owns gate-row g: w_hh[g][:] in 64 packed f32x2 registers.
// h loads from smem via LDS.128 (ulonglong2).
// ---------------------------------------------------------------------------
__global__ void __launch_bounds__(384, 1)
gru_kernel(const float* __restrict__ a_in, const float* __restrict__ p_in,
           const float* __restrict__ n_in,
           const int* __restrict__ a_len, const int* __restrict__ p_len,
           const int* __restrict__ n_len,
           const float* __restrict__ w_ih, const float* __restrict__ w_hh,
           const float* __restrict__ b_ih, const float* __restrict__ b_hh)
{
    const int s  = blockIdx.x;          // 0..95
    const int br = s >> 5;
    const int b  = s & 31;
    const float* inp = (br == 0 ? a_in : (br == 1 ? p_in : n_in)) + b * TT * 4;
    const int* lens  = (br == 0 ? a_len : (br == 1 ? p_len : n_len));
    const int len    = lens[b];

    const int g = threadIdx.x;          // 0..383

    const float wih0 = w_ih[g * 2 + 0];
    const float wih1 = w_ih[g * 2 + 1];
    const float bih  = b_ih[g];
    const float bhh  = b_hh[g];

    ull w2[64];
    {
        const ulonglong2* wr = (const ulonglong2*)(w_hh + g * EE);
#pragma unroll
        for (int i = 0; i < 32; ++i) {
            const ulonglong2 t = wr[i];
            w2[2 * i + 0] = t.x;
            w2[2 * i + 1] = t.y;
        }
    }

    __shared__ __align__(16) float hsf[EE];
    __shared__ float hg[G3];
    __shared__ float xgs[G3];

    if (g < EE) hsf[g] = 0.0f;
    __syncthreads();

    const ulonglong2* hs4 = (const ulonglong2*)hsf;

    for (int t = 0; t < TT; ++t) {
        const float2 x01 = *(const float2*)(inp + t * 4);
        xgs[g] = fmaf(wih0, x01.x, fmaf(wih1, x01.y, bih));

        ull acc0 = 0ull, acc1 = 0ull, acc2 = 0ull, acc3 = 0ull;
#pragma unroll
        for (int i = 0; i < 16; ++i) {
            const ulonglong2 h01 = hs4[2 * i + 0];
            const ulonglong2 h23 = hs4[2 * i + 1];
            acc0 = f2fma(w2[4 * i + 0], h01.x, acc0);
            acc1 = f2fma(w2[4 * i + 1], h01.y, acc1);
            acc2 = f2fma(w2[4 * i + 2], h23.x, acc2);
            acc3 = f2fma(w2[4 * i + 3], h23.y, acc3);
        }
        hg[g] = (hsum2(acc0) + hsum2(acc1)) + (hsum2(acc2) + hsum2(acc3)) + bhh;
        __syncthreads();

        if (g < EE) {
            const float r  = fsigmoid(xgs[g] + hg[g]);
            const float z  = fsigmoid(xgs[g + 128] + hg[g + 128]);
            const float nn = ftanh(fmaf(r, hg[g + 256], xgs[g + 256]));
            const float h2 = fmaf(z, hsf[g] - nn, nn);   // (1-z)*n + z*h
            hsf[g] = h2;
            if (t == len - 1) g_coor[s * EE + g] = h2;
        }
        __syncthreads();
    }
}

// ---------------------------------------------------------------------------
// Kernel 2: fused m + QKV GEMM.
// C[49152 x 384] = m @ attn_in_w^T + b.  128x128 tiles (one col tile per
// q/k/v part), K in two 64-chunks, 8x8 micro-tiles with f32x2 accumulators.
// Epilogue stages C through smem; coalesced float4 stores to t-major q/k/v.
// ---------------------------------------------------------------------------
#define TSTR 136

__global__ void __launch_bounds__(256)
qkv_gemm_kernel(const float* __restrict__ a_in, const float* __restrict__ p_in,
                const float* __restrict__ n_in,
                const float* __restrict__ lw, const float* __restrict__ lb,
                const float* __restrict__ pw, const float* __restrict__ pb,
                const float* __restrict__ in_w, const float* __restrict__ in_b)
{
    const int bx   = blockIdx.x;     // 0..383 : s = bx>>2, t0 = (bx&3)*128
    const int part = blockIdx.y;     // 0..2   : q / k / v
    const int s  = bx >> 2;
    const int t0 = (bx & 3) * 128;
    const int tid = threadIdx.x;
    const int tx = tid & 15;
    const int ty = tid >> 4;

    extern __shared__ __align__(16) float dynsm[];
    float* As = dynsm;                 // [64][TSTR]
    float* Bs = dynsm + 64 * TSTR;     // [64][TSTR]
    float* Cs = dynsm;                 // [128][TSTR] (aliases As+Bs exactly)

    __shared__ float rg0[128], rg1[128], rsn[128], rcs[128];
    __shared__ float lw0s[128], lw1s[128], lbs[128];
    __shared__ float pw0s[128], pw1s[128], pbs[128];
    __shared__ float bias_s[128];

    if (tid < 128) {
        const int t = t0 + tid;
        const int br = s >> 5;
        const int b = s & 31;
        const float* inp = (br == 0 ? a_in : (br == 1 ? p_in : n_in));
        const float2 gg = *(const float2*)(inp + ((b << 9) + t) * 4 + 2);
        rg0[tid] = gg.x;
        rg1[tid] = gg.y;
        rsn[tid] = sinf((float)t);
        rcs[tid] = cosf((float)t);
        lw0s[tid] = lw[2 * tid];
        lw1s[tid] = lw[2 * tid + 1];
        lbs[tid]  = lb[tid];
        pw0s[tid] = pw[2 * tid];
        pw1s[tid] = pw[2 * tid + 1];
        pbs[tid]  = pb[tid];
        bias_s[tid] = in_b[part * 128 + tid];
    }
    __syncthreads();

    ull acc2[8][4];
#pragma unroll
    for (int i = 0; i < 8; ++i)
#pragma unroll
        for (int j = 0; j < 4; ++j) acc2[i][j] = 0ull;

    for (int kc = 0; kc < 2; ++kc) {
        // A tile: compute m for 64 k-rows x 128 t-cols
        for (int idx = tid; idx < 64 * 128; idx += 256) {
            const int kk = idx >> 7;
            const int tl = idx & 127;
            const int k = kc * 64 + kk;
            const float g0 = rg0[tl], g1 = rg1[tl];
            float m = fmaf(lw0s[k], g0, fmaf(lw1s[k], g1, lbs[k]));
            m += fmaf(pw0s[k], g0 + rsn[tl],
                      fmaf(pw1s[k], g1 + rcs[tl], pbs[k]));
            As[kk * TSTR + tl] = m;
        }
        // B tile: in_w rows (coalesced 64-float global runs)
        for (int idx = tid; idx < 64 * 128; idx += 256) {
            const int kkl = idx & 63;
            const int cl  = idx >> 6;
            Bs[kkl * TSTR + cl] = in_w[(part * 128 + cl) * EE + kc * 64 + kkl];
        }
        __syncthreads();

#pragma unroll 4
        for (int kk = 0; kk < 64; ++kk) {
            const float4 a0 = *(const float4*)(As + kk * TSTR + ty * 8);
            const float4 a1 = *(const float4*)(As + kk * TSTR + ty * 8 + 4);
            const ulonglong2 b01 = *(const ulonglong2*)(Bs + kk * TSTR + tx * 8);
            const ulonglong2 b23 = *(const ulonglong2*)(Bs + kk * TSTR + tx * 8 + 4);
            const float av[8] = {a0.x, a0.y, a0.z, a0.w, a1.x, a1.y, a1.z, a1.w};
#pragma unroll
            for (int i = 0; i < 8; ++i) {
                const ull ap = f2pack(av[i], av[i]);
                acc2[i][0] = f2fma(ap, b01.x, acc2[i][0]);
                acc2[i][1] = f2fma(ap, b01.y, acc2[i][1]);
                acc2[i][2] = f2fma(ap, b23.x, acc2[i][2]);
                acc2[i][3] = f2fma(ap, b23.y, acc2[i][3]);
            }
        }
        __syncthreads();
    }

    // epilogue: stage C in smem (aliases As/Bs; safe after the trailing sync)
#pragma unroll
    for (int i = 0; i < 8; ++i) {
        const int r = ty * 8 + i;
#pragma unroll
        for (int j = 0; j < 4; ++j)
            *(ull*)(Cs + r * TSTR + tx * 8 + 2 * j) = acc2[i][j];
    }
    __syncthreads();

    float* G = (part == 0 ? g_q : (part == 1 ? g_k : g_v));
    for (int it = 0; it < 8; ++it) {
        const int idx = it * 256 + tid;
        const int tl = idx & 127;
        const int hq = idx >> 7;       // head 0..15
        float4 c0 = *(const float4*)(Cs + tl * TSTR + hq * 8);
        float4 c1 = *(const float4*)(Cs + tl * TSTR + hq * 8 + 4);
        c0.x += bias_s[hq * 8 + 0]; c0.y += bias_s[hq * 8 + 1];
        c0.z += bias_s[hq * 8 + 2]; c0.w += bias_s[hq * 8 + 3];
        c1.x += bias_s[hq * 8 + 4]; c1.y += bias_s[hq * 8 + 5];
        c1.z += bias_s[hq * 8 + 6]; c1.w += bias_s[hq * 8 + 7];
        const int addr = (s * NHH + hq) * 4096 + (t0 + tl) * 8;
        *(float4*)(G + addr)     = c0;
        *(float4*)(G + addr + 4) = c1;
    }
}

// ---------------------------------------------------------------------------
// Kernel 3: attention per (s, h) block (1536 blocks, 256 threads).
// t-major k/v in smem; each LANE owns 2 whole queries; k/v broadcast LDS.128.
// No-max softmax (scores O(3e-3)); scale*log2e folded into q; o mean-pooled.
// ---------------------------------------------------------------------------
__global__ void __launch_bounds__(256)
attn_kernel()
{
    const int bh = blockIdx.x;          // 0..1535
    const int s = bh >> 4;
    const int tid = threadIdx.x;
    const int w = tid >> 5;
    const int lane = tid & 31;

    __shared__ __align__(16) float ks[TT * HDD];
    __shared__ __align__(16) float vs[TT * HDD];
    __shared__ float osum_s[8][8];

    {
        const float4* kg = (const float4*)(g_k + bh * 4096);
        const float4* vg = (const float4*)(g_v + bh * 4096);
        float4* k4 = (float4*)ks;
        float4* v4 = (float4*)vs;
        for (int i = tid; i < 1024; i += 256) {
            k4[i] = kg[i];
            v4[i] = vg[i];
        }
    }
    __syncthreads();

    const float cst = 0.35355339059327373f * 1.4426950408889634f;

    ull qa[2][4];
    {
        const float* qp = g_q + bh * 4096;
        const int qi[2] = { w * 64 + lane, w * 64 + lane + 32 };
#pragma unroll
        for (int qq = 0; qq < 2; ++qq) {
            const float4 x0 = *(const float4*)(qp + qi[qq] * 8);
            const float4 x1 = *(const float4*)(qp + qi[qq] * 8 + 4);
            qa[qq][0] = f2pack(x0.x * cst, x0.y * cst);
            qa[qq][1] = f2pack(x0.z * cst, x0.w * cst);
            qa[qq][2] = f2pack(x1.x * cst, x1.y * cst);
            qa[qq][3] = f2pack(x1.z * cst, x1.w * cst);
        }
    }

    ull pv[2][4];
    float sume[2] = {0.0f, 0.0f};
#pragma unroll
    for (int qq = 0; qq < 2; ++qq)
#pragma unroll
        for (int j = 0; j < 4; ++j) pv[qq][j] = 0ull;

#pragma unroll 4
    for (int t = 0; t < TT; ++t) {
        const ulonglong2 k01 = *(const ulonglong2*)(ks + t * 8);
        const ulonglong2 k23 = *(const ulonglong2*)(ks + t * 8 + 4);
        const ulonglong2 v01 = *(const ulonglong2*)(vs + t * 8);
        const ulonglong2 v23 = *(const ulonglong2*)(vs + t * 8 + 4);
#pragma unroll
        for (int qq = 0; qq < 2; ++qq) {
            ull sa = f2fma(qa[qq][0], k01.x, 0ull);
            sa = f2fma(qa[qq][1], k01.y, sa);
            sa = f2fma(qa[qq][2], k23.x, sa);
            sa = f2fma(qa[qq][3], k23.y, sa);
            const float p = fex2(hsum2(sa));   // exp(score)
            sume[qq] += p;
            const ull pp = f2pack(p, p);
            pv[qq][0] = f2fma(pp, v01.x, pv[qq][0]);
            pv[qq][1] = f2fma(pp, v01.y, pv[qq][1]);
            pv[qq][2] = f2fma(pp, v23.x, pv[qq][2]);
            pv[qq][3] = f2fma(pp, v23.y, pv[qq][3]);
        }
    }

    float oacc[8];
#pragma unroll
    for (int d = 0; d < 8; ++d) oacc[d] = 0.0f;
#pragma unroll
    for (int qq = 0; qq < 2; ++qq) {
        const float inv = 1.0f / sume[qq];
#pragma unroll
        for (int j = 0; j < 4; ++j) {
            float x, y;
            f2unpack(pv[qq][j], x, y);
            oacc[2 * j]     = fmaf(x, inv, oacc[2 * j]);
            oacc[2 * j + 1] = fmaf(y, inv, oacc[2 * j + 1]);
        }
    }
#pragma unroll
    for (int d = 0; d < 8; ++d) {
#pragma unroll
        for (int off = 16; off > 0; off >>= 1)
            oacc[d] += __shfl_xor_sync(0xffffffffu, oacc[d], off);
    }
    if (lane == 0) {
#pragma unroll
        for (int d = 0; d < 8; ++d) osum_s[w][d] = oacc[d];
    }
    __syncthreads();
    if (tid < 8) {
        float t = 0.0f;
#pragma unroll
        for (int ww = 0; ww < 8; ++ww) t += osum_s[ww][tid];
        g_omean[s * EE + (bh & 15) * 8 + tid] = t * (1.0f / 512.0f);
    }
}

// ---------------------------------------------------------------------------
// Kernel 4: output projection of mean + mix.  Warp-per-32-outputs with
// coalesced float4 row loads and butterfly reduction (R3 version was
// uncoalesced-latency-bound: 14us, occ 6%, issue 2%).
// ---------------------------------------------------------------------------
__global__ void __launch_bounds__(128)
proj_kernel(const float* __restrict__ out_w, const float* __restrict__ out_b,
            const float* __restrict__ gamma_p, float* __restrict__ out)
{
    const int s = blockIdx.x;       // 0..95
    const int tid = threadIdx.x;    // 0..127
    const int w = tid >> 5;
    const int lane = tid & 31;

    __shared__ __align__(16) float4 om4[32];
    if (tid < 32) om4[tid] = ((const float4*)(g_omean + s * EE))[tid];
    __syncthreads();

    const float4 mo = om4[lane];
    float myacc = 0.0f;

#pragma unroll 8
    for (int i = 0; i < 32; ++i) {
        const int e = w * 32 + i;
        const float4 r = __ldg((const float4*)(out_w + e * EE) + lane);
        float p = fmaf(r.x, mo.x, fmaf(r.y, mo.y, fmaf(r.z, mo.z, r.w * mo.w)));
#pragma unroll
        for (int off = 16; off > 0; off >>= 1)
            p += __shfl_xor_sync(0xffffffffu, p, off);
        if (lane == i) myacc = p;
    }

    const int e = w * 32 + lane;
    const float g = *gamma_p;
    out[s * EE + e] = g * g_coor[s * EE + e] + (1.0f - g) * (myacc + out_b[e]);
}

// ---------------------------------------------------------------------------
// Kernel 5: triplet distances.
// ---------------------------------------------------------------------------
__global__ void __launch_bounds__(128)
dist_kernel(float* __restrict__ out)
{
    const int b = blockIdx.x;   // 0..31
    const int e = threadIdx.x;  // 0..127

    const float av = out[b * EE + e];
    const float pe = out[4096 + b * EE + e];
    const float ne = out[8192 + b * EE + e];
    const float dp = av - pe + 1e-6f;
    const float dn = av - ne + 1e-6f;
    float sp = dp * dp;
    float sn = dn * dn;
#pragma unroll
    for (int off = 16; off > 0; off >>= 1) {
        sp += __shfl_xor_sync(0xffffffffu, sp, off);
        sn += __shfl_xor_sync(0xffffffffu, sn, off);
    }
    __shared__ float rp[4], rn[4];
    if ((e & 31) == 0) { rp[e >> 5] = sp; rn[e >> 5] = sn; }
    __syncthreads();
    if (e == 0) {
        const float tp = rp[0] + rp[1] + rp[2] + rp[3];
        const float tn = rn[0] + rn[1] + rn[2] + rn[3];
        out[12288 + b] = expf(-sqrtf(tp));
        out[12320 + b] = expf(-sqrtf(tn));
    }
}

// ---------------------------------------------------------------------------
// Side-stream infrastructure for GRU || (QKV -> attn) overlap.
// Created once on the first (non-captured) correctness call; captured calls
// only record/wait events — the canonical capturable fork-join pattern.
// No device memory is allocated (streams/events are host-side objects).
// ---------------------------------------------------------------------------
struct SideStream {
    cudaStream_t s;
    cudaEvent_t fork, join;
    SideStream() {
        cudaStreamCreateWithFlags(&s, cudaStreamNonBlocking);
        cudaEventCreateWithFlags(&fork, cudaEventDisableTiming);
        cudaEventCreateWithFlags(&join, cudaEventDisableTiming);
    }
};
static SideStream& side() { static SideStream ss; return ss; }

// ---------------------------------------------------------------------------
// Launch
// ---------------------------------------------------------------------------
extern "C" void kernel_launch(void* const* d_in, const int* in_sizes, int n_in,
                              void* d_out, int out_size)
{
    const float* anchor = (const float*)d_in[0];
    const float* pos    = (const float*)d_in[1];
    const float* neg    = (const float*)d_in[2];
    const int*   alen   = (const int*)d_in[3];
    const int*   plen   = (const int*)d_in[4];
    const int*   nlen   = (const int*)d_in[5];
    const float* w_ih   = (const float*)d_in[6];
    const float* w_hh   = (const float*)d_in[7];
    const float* b_ih   = (const float*)d_in[8];
    const float* b_hh   = (const float*)d_in[9];
    const float* lw     = (const float*)d_in[10];
    const float* lb     = (const float*)d_in[11];
    const float* pw     = (const float*)d_in[12];
    const float* pb     = (const float*)d_in[13];
    const float* in_w   = (const float*)d_in[14];
    const float* in_b   = (const float*)d_in[15];
    const float* out_w  = (const float*)d_in[16];
    const float* out_b  = (const float*)d_in[17];
    const float* gamma  = (const float*)d_in[18];
    float* out = (float*)d_out;

    // One-time setup on the first (uncaptured correctness) call: nothing but
    // stream ops happens inside the captured region on later calls.
    static bool init_done = false;
    if (!init_done) {
        const int smem = 2 * 64 * TSTR * (int)sizeof(float);   // 69632 B
        cudaFuncSetAttribute(qkv_gemm_kernel,
                             cudaFuncAttributeMaxDynamicSharedMemorySize, smem);
        side();   // create stream + events now
        init_done = true;
    }

    const int qkv_smem = 2 * 64 * TSTR * (int)sizeof(float);
    SideStream& ss = side();

    // fork: GRU on side stream, grid branch on the main (capture) stream
    cudaEventRecord(ss.fork, 0);
    cudaStreamWaitEvent(ss.s, ss.fork, 0);
    gru_kernel<<<BBS, 384, 0, ss.s>>>(anchor, pos, neg, alen, plen, nlen,
                                      w_ih, w_hh, b_ih, b_hh);
    cudaEventRecord(ss.join, ss.s);

    qkv_gemm_kernel<<<dim3(384, 3), 256, qkv_smem>>>(anchor, pos, neg,
                                                     lw, lb, pw, pb, in_w, in_b);
    attn_kernel<<<BBS * NHH, 256>>>();

    // join: proj needs both branches
    cudaStreamWaitEvent(0, ss.join, 0);
    proj_kernel<<<BBS, 128>>>(out_w, out_b, gamma, out);
    dist_kernel<<<BATCH, 128>>>(out);
}